// round 13
// baseline (speedup 1.0000x reference)
#include <cuda_runtime.h>
#include <cstdint>

// TranVectorQuantizer: latent [16384,8,32] f32, codebook [128,32] f32.
// Outputs concatenated in d_out (all f32):
//   [0,        4194304)  policy_vq_latent = latent + (quantized - latent)
//   [4194304,  8388608)  quantized_latent = codebook[argmin_j dist(x, c_j)]
//   [8388608, 75497472)  codebook_set = codebook tiled 16384x
//
// Distance reproduces the reference arithmetic EXACTLY (rel_err 0.0 verified
// R3/R4/R7/R8/R11/R12): d_j = fmaf(-2, M_j, fl(A + B_j)), fixed f32x2 FMA
// chain order. DO NOT change the FMA chain order or the snapping add:
// tie-breaking on the ~ulp(32) distance grid depends on it.
//
// R13: split-codebook warp pairing. 2 rows/thread (R12's proven L1 win) but
// TWO warps per row-pair: tid<64 scans codes [0,64), tid>=64 scans [64,128)
// for the SAME rows; results combined exactly via smem (strict < keeps the
// lower index on ties => identical argmin). Doubles resident warps
// (2048->4096) at unchanged per-row LDS/FMA totals. Interleaved broadcast
// stores (128/thread) + coalesced smem-bi epilogue, both proven.

#define DDIM 32
#define KCODES 128

static __device__ __forceinline__ void upk2(unsigned long long p, float& a, float& b) {
    asm("mov.b64 {%0, %1}, %2;" : "=f"(a), "=f"(b) : "l"(p));
}
static __device__ __forceinline__ unsigned long long pk2(float a, float b) {
    unsigned long long r;
    asm("mov.b64 %0, {%1, %2};" : "=l"(r) : "f"(a), "f"(b));
    return r;
}
static __device__ __forceinline__ void fma2(unsigned long long& acc,
                                            unsigned long long x,
                                            unsigned long long c) {
    asm("fma.rn.f32x2 %0, %1, %2, %0;" : "+l"(acc) : "l"(x), "l"(c));
}

// ---- exact kernel: n_rows == 131072; grid 1024 x 128 ----------------------
// Each block owns 128 rows. Thread t (t<64) and thread t+64 both hold rows
// (bid*128+t, bid*128+t+64); the low half scans codes 0..63, the high half
// codes 64..127. smem combine picks the global first argmin exactly.
__global__ void __launch_bounds__(128, 5) vq2s_kernel(
    const float* __restrict__ latent,
    const float* __restrict__ cb,
    float* __restrict__ out,
    int n_rows)
{
    __shared__ float s_cb[KCODES * DDIM];   // 16 KB
    __shared__ float s_nrm[KCODES];
    __shared__ float s_bd[256];             // bestA[128], bestB[128] per thread
    __shared__ int   s_bj[256];
    __shared__ int   s_bi[128];             // final per-row winner

    const int tid  = threadIdx.x;
    const int bid  = blockIdx.x;
    const int half = tid >> 6;               // 0: codes 0..63, 1: codes 64..127
    const int lane64 = tid & 63;
    const int gt   = bid * 128 + tid;        // 0..131071 (store-stream id)
    const int rowA = bid * 128 + lane64;
    const int rowB = rowA + 64;

    // ---- load both rows directly as f32x2 packs (bit-identical to float4) --
    const ulonglong2* la = reinterpret_cast<const ulonglong2*>(latent) + (size_t)rowA * 8;
    const ulonglong2* lb = reinterpret_cast<const ulonglong2*>(latent) + (size_t)rowB * 8;
    unsigned long long xA0[8], xA1[8], xB0[8], xB1[8];
    #pragma unroll
    for (int k = 0; k < 8; k++) { ulonglong2 u = la[k]; xA0[k] = u.x; xA1[k] = u.y; }
    #pragma unroll
    for (int k = 0; k < 8; k++) { ulonglong2 u = lb[k]; xB0[k] = u.x; xB1[k] = u.y; }

    // ---- stage codebook ----
    float4* s_cb4 = reinterpret_cast<float4*>(s_cb);
    const float4* cb4 = reinterpret_cast<const float4*>(cb);
    #pragma unroll
    for (int i = 0; i < 8; i++) s_cb4[tid + i * 128] = cb4[tid + i * 128];
    __syncthreads();

    {   // same norm accumulation order as all passing versions
        float s = 0.f;
        #pragma unroll
        for (int d = 0; d < DDIM; d++) { float v = s_cb[tid * DDIM + d]; s += v * v; }
        s_nrm[tid] = s;
    }
    __syncthreads();

    // ---- A = ||x||^2 per row: unpack packs, EXACT original fmaf order ------
    float AA, AB;
    {
        float a0 = 0.f, a1 = 0.f, a2 = 0.f, a3 = 0.f;
        #pragma unroll
        for (int k = 0; k < 8; k++) {
            float x0, x1, x2, x3;
            upk2(xA0[k], x0, x1); upk2(xA1[k], x2, x3);
            a0 = fmaf(x0, x0, a0); a1 = fmaf(x1, x1, a1);
            a2 = fmaf(x2, x2, a2); a3 = fmaf(x3, x3, a3);
        }
        AA = (a0 + a1) + (a2 + a3);
    }
    {
        float a0 = 0.f, a1 = 0.f, a2 = 0.f, a3 = 0.f;
        #pragma unroll
        for (int k = 0; k < 8; k++) {
            float x0, x1, x2, x3;
            upk2(xB0[k], x0, x1); upk2(xB1[k], x2, x3);
            a0 = fmaf(x0, x0, a0); a1 = fmaf(x1, x1, a1);
            a2 = fmaf(x2, x2, a2); a3 = fmaf(x3, x3, a3);
        }
        AB = (a0 + a1) + (a2 + a3);
    }

    const size_t n_lat = (size_t)n_rows * DDIM;
    float4* out_cs4 = reinterpret_cast<float4*>(out + 2 * n_lat);
    const size_t nth = (size_t)gridDim.x * 128;    // 131072, multiple of 1024

    float bestA = 3.0e38f, bestB = 3.0e38f;
    int   biA = 0, biB = 0;
    const ulonglong2* scb2 = reinterpret_cast<const ulonglong2*>(s_cb);

    // stride preserves (index & 1023): one register-held broadcast value
    float4 vbc = s_cb4[gt & 1023];
    float4* csp = out_cs4 + gt;

    const int jbase = half << 6;                   // 0 or 64 (warp-uniform)
    #pragma unroll 2
    for (int jj = 0; jj < 64; jj++) {
        __stcs(csp, vbc);                // 2 interleaved codebook_set stores
        __stcs(csp + nth, vbc);
        csp += 2 * nth;

        const int j = jbase + jj;
        unsigned long long aA0 = 0ull, aA1 = 0ull, aB0 = 0ull, aB1 = 0ull;
        const ulonglong2* cj = scb2 + j * 8;       // broadcast LDS (warp-uniform j)
        #pragma unroll
        for (int k = 0; k < 8; k++) {
            ulonglong2 c = cj[k];
            fma2(aA0, xA0[k], c.x);
            fma2(aA1, xA1[k], c.y);
            fma2(aB0, xB0[k], c.x);
            fma2(aB1, xB1[k], c.y);
        }
        float nrm = s_nrm[j];
        unsigned long long sA, sB;
        asm("add.rn.f32x2 %0, %1, %2;" : "=l"(sA) : "l"(aA0), "l"(aA1));
        asm("add.rn.f32x2 %0, %1, %2;" : "=l"(sB) : "l"(aB0), "l"(aB1));
        float lo, hi;
        upk2(sA, lo, hi);
        float dA = fmaf(-2.0f, lo + hi, AA + nrm);   // fl(S - 2M), single rounding
        upk2(sB, lo, hi);
        float dB = fmaf(-2.0f, lo + hi, AB + nrm);
        if (dA < bestA) { bestA = dA; biA = j; }     // strict <: first index on ties
        if (dB < bestB) { bestB = dB; biB = j; }
    }

    // ---- combine halves: global first-argmin (exact comparisons) ----------
    s_bd[tid]       = bestA;  s_bj[tid]       = biA;
    s_bd[tid + 128] = bestB;  s_bj[tid + 128] = biB;
    __syncthreads();
    if (half == 0) {
        float dA2 = s_bd[tid + 64];          // high half, same rowA
        if (dA2 < bestA) biA = s_bj[tid + 64];   // strict <: lower index wins ties
        float dB2 = s_bd[tid + 192];         // high half, same rowB
        if (dB2 < bestB) biB = s_bj[tid + 192];
        s_bi[lane64]      = biA;
        s_bi[lane64 + 64] = biB;
    }
    __syncthreads();

    // ---- coalesced epilogue (proven): smem bi handoff, x re-read from L2 ---
    const size_t baseF4 = (size_t)bid * 128 * 8;   // block's first float4
    const float4* lat4 = reinterpret_cast<const float4*>(latent) + baseF4;
    float4* op = reinterpret_cast<float4*>(out) + baseF4;
    float4* oq = reinterpret_cast<float4*>(out + n_lat) + baseF4;
    #pragma unroll
    for (int i = 0; i < 8; i++) {
        int f   = tid + i * 128;
        int row = f >> 3;
        int c   = f & 7;
        float4 q = s_cb4[s_bi[row] * 8 + c];
        float4 x = __ldg(lat4 + f);
        float4 p;
        p.x = x.x + (q.x - x.x);
        p.y = x.y + (q.y - x.y);
        p.z = x.z + (q.z - x.z);
        p.w = x.w + (q.w - x.w);
        __stcs(oq + f, q);
        __stcs(op + f, p);
    }
}

// ---------------- generic fallback: 1 row/thread (R4-proven) ----------------
__global__ void __launch_bounds__(128, 8) vq_fused1_kernel(
    const float* __restrict__ latent,
    const float* __restrict__ cb,
    float* __restrict__ out,
    int n_rows)
{
    __shared__ float s_cb[KCODES * DDIM];
    __shared__ float s_nrm[KCODES];

    const int tid  = threadIdx.x;
    const int gtid = blockIdx.x * 128 + tid;
    const bool active = gtid < n_rows;

    float4 xv[8];
    const float4* xr4 = reinterpret_cast<const float4*>(latent) + (size_t)gtid * 8;
    if (active) {
        #pragma unroll
        for (int k = 0; k < 8; k++) xv[k] = xr4[k];
    }

    float4* s_cb4 = reinterpret_cast<float4*>(s_cb);
    const float4* cb4 = reinterpret_cast<const float4*>(cb);
    #pragma unroll
    for (int i = 0; i < 8; i++) s_cb4[tid + i * 128] = cb4[tid + i * 128];
    __syncthreads();

    {
        float s = 0.f;
        #pragma unroll
        for (int d = 0; d < DDIM; d++) { float v = s_cb[tid * DDIM + d]; s += v * v; }
        s_nrm[tid] = s;
    }
    __syncthreads();

    const size_t n_lat = (size_t)n_rows * DDIM;
    float* out_quant = out + n_lat;
    float4* out_cs4  = reinterpret_cast<float4*>(out + 2 * n_lat);
    const size_t nth = (size_t)gridDim.x * 128;

    unsigned long long xp0[8], xp1[8];
    float A = 0.f;
    if (active) {
        float a0 = 0.f, a1 = 0.f, a2 = 0.f, a3 = 0.f;
        #pragma unroll
        for (int k = 0; k < 8; k++) {
            a0 = fmaf(xv[k].x, xv[k].x, a0);
            a1 = fmaf(xv[k].y, xv[k].y, a1);
            a2 = fmaf(xv[k].z, xv[k].z, a2);
            a3 = fmaf(xv[k].w, xv[k].w, a3);
            xp0[k] = pk2(xv[k].x, xv[k].y);
            xp1[k] = pk2(xv[k].z, xv[k].w);
        }
        A = (a0 + a1) + (a2 + a3);
    }

    const size_t total4 = (size_t)n_rows * 128;
    for (size_t i4 = (size_t)gtid; i4 < total4; i4 += nth)
        __stcs(&out_cs4[i4], s_cb4[i4 & 1023]);

    if (!active) return;

    float best = 3.0e38f;
    int   bi   = 0;
    const ulonglong2* scb2 = reinterpret_cast<const ulonglong2*>(s_cb);
    #pragma unroll 2
    for (int j = 0; j < KCODES; j++) {
        unsigned long long acc0 = 0ull, acc1 = 0ull;
        const ulonglong2* cj = scb2 + j * 8;
        #pragma unroll
        for (int k = 0; k < 8; k++) {
            ulonglong2 c = cj[k];
            fma2(acc0, xp0[k], c.x);
            fma2(acc1, xp1[k], c.y);
        }
        unsigned long long accs;
        asm("add.rn.f32x2 %0, %1, %2;" : "=l"(accs) : "l"(acc0), "l"(acc1));
        float lo, hi; upk2(accs, lo, hi);
        float d = fmaf(-2.0f, lo + hi, A + s_nrm[j]);
        if (d < best) { best = d; bi = j; }
    }

    const float4* q4 = reinterpret_cast<const float4*>(s_cb + bi * DDIM);
    float4* oq = reinterpret_cast<float4*>(out_quant) + (size_t)gtid * 8;
    float4* op = reinterpret_cast<float4*>(out)       + (size_t)gtid * 8;
    #pragma unroll
    for (int k = 0; k < 8; k++) {
        float4 q = q4[k];
        __stcs(oq + k, q);
        float xx, xy, xz, xw;
        upk2(xp0[k], xx, xy); upk2(xp1[k], xz, xw);
        float4 p;
        p.x = xx + (q.x - xx); p.y = xy + (q.y - xy);
        p.z = xz + (q.z - xz); p.w = xw + (q.w - xw);
        __stcs(op + k, p);
    }
}

extern "C" void kernel_launch(void* const* d_in, const int* in_sizes, int n_in,
                              void* d_out, int out_size)
{
    const float* latent = (const float*)d_in[0];
    const float* cb     = (const float*)d_in[1];
    int sz0 = in_sizes[0], sz1 = in_sizes[1];
    if (sz0 < sz1) {  // safety: latent is the big tensor
        const float* t = latent; latent = cb; cb = t;
        int ts = sz0; sz0 = sz1; sz1 = ts;
    }
    (void)n_in; (void)out_size;
    int n_rows = sz0 / DDIM;                         // 131072
    if (n_rows == 131072) {
        vq2s_kernel<<<1024, 128>>>(latent, cb, (float*)d_out, n_rows);
    } else {
        vq_fused1_kernel<<<(n_rows + 127) / 128, 128>>>(latent, cb, (float*)d_out, n_rows);
    }
}